// round 4
// baseline (speedup 1.0000x reference)
#include <cuda_runtime.h>

#define Ec   128
#define Wc   128
#define Vc   7
#define Sc   2048
#define Bc   16
#define GBLK 128                 // g blocks (one per e)
#define NT   128

// Scratch (flags reset at end of every run -> deterministic across replays)
__device__ int   d_tok[Bc * Wc];     // window tokens, 7 = pad sentinel
__device__ float d_part[Bc * GBLK];  // per-(b, e) partial sums
__device__ int   d_tokready;         // counter blocks completed
__device__ int   d_arrive;           // g blocks completed

__global__ void __launch_bounds__(NT, 1)
fused_kernel(const void* __restrict__ xraw,
             const float* __restrict__ emb,
             const float* __restrict__ fc_w,
             const float* __restrict__ fc_b,
             const float* __restrict__ out_w,
             const float* __restrict__ out_b,
             float* __restrict__ out) {
    const int blk = blockIdx.x;
    const int k   = threadIdx.x;

    if (blk >= GBLK) {
        // ================= counter block: batch b =================
        const int b = blk - GBLK;
        __shared__ int   sred[NT / 32];
        __shared__ float sc0;

        // dtype detection: tokens in [0,7) => int64 iff all odd 32-bit words
        // of the first 8KB are zero (8KB in-bounds for both layouts).
        const int* xw = (const int*)xraw;
        int any = 0;
        for (int i = k; i < 2048; i += NT)
            if ((i & 1) && xw[i] != 0) any = 1;
        any = __any_sync(0xffffffffu, any) ? 1 : 0;
        if ((k & 31) == 0) sred[k >> 5] = any;
        __syncthreads();
        const int is32 = sred[0] | sred[1] | sred[2] | sred[3];
        __syncthreads();

        // count non-pad tokens in row b
        int cnt = 0;
        if (is32) {
            const int* xr = (const int*)xraw + b * Sc;
            for (int s = k; s < Sc; s += NT) cnt += (xr[s] != 0);
        } else {
            const long long* xr = (const long long*)xraw + b * Sc;
            for (int s = k; s < Sc; s += NT) cnt += (xr[s] != 0);
        }
#pragma unroll
        for (int off = 16; off; off >>= 1)
            cnt += __shfl_down_sync(0xffffffffu, cnt, off);
        if ((k & 31) == 0) sred[k >> 5] = cnt;
        __syncthreads();
        const int t = (sred[0] + sred[1] + sred[2] + sred[3]) - 1;

        // publish window tokens (7 = pad sentinel -> zero emb row)
        const int p = t - (Wc - 1) + k;
        int tok = Vc;
        if (p >= 0)
            tok = is32 ? ((const int*)xraw)[b * Sc + p]
                       : (int)((const long long*)xraw)[b * Sc + p];
        d_tok[b * Wc + k] = tok;
        __threadfence();
        __syncthreads();
        if (k == 0) atomicAdd(&d_tokready, 1);

        if (b != 0) return;

        // ---- block b==0 doubles as the final reducer ----
        // c0 = out_b + dot(out_w, fc_b), computed while g-blocks run
        float c = out_w[k] * fc_b[k];
#pragma unroll
        for (int off = 16; off; off >>= 1)
            c += __shfl_down_sync(0xffffffffu, c, off);
        __shared__ float scc[NT / 32];
        if ((k & 31) == 0) scc[k >> 5] = c;
        __syncthreads();
        if (k == 0) sc0 = scc[0] + scc[1] + scc[2] + scc[3] + out_b[0];

        if (k == 0)
            while (*(volatile int*)&d_arrive < GBLK) __nanosleep(32);
        __syncthreads();
        __threadfence();

        // thread k: batch bb = k/8, e-slice i = k%8 (16 contiguous e's each)
        const int bb = k >> 3, i = k & 7;
        float s = 0.0f;
#pragma unroll
        for (int j = 0; j < 16; j++)
            s += d_part[bb * GBLK + i * 16 + j];
#pragma unroll
        for (int off = 4; off; off >>= 1)
            s += __shfl_down_sync(0xffffffffu, s, off, 8);
        if (i == 0) out[bb] = s + sc0;

        __syncthreads();
        if (k == 0) {               // reset flags for next replay
            d_arrive = 0;
            d_tokready = 0;
            __threadfence();
        }
        return;
    }

    // ================= g block: e = blk =================
    const int e = blk;
    __shared__ float s_w[Ec];
    __shared__ float s_emb[8 * 129];     // row 7 zeroed (pad sentinel)
    __shared__ float sp[Bc][NT / 32];

    s_w[k] = out_w[k];
    for (int i = k; i < 8 * Ec; i += NT)
        s_emb[(i >> 7) * 129 + (i & 127)] = (i < Vc * Ec) ? emb[i] : 0.0f;
    __syncthreads();

    // g[e*128+k] in register: 8MB fc_w stream, coalesced
    const float* fw = fc_w + e * Wc + k;
    float acc = 0.0f;
#pragma unroll 32
    for (int o = 0; o < Ec; o++)
        acc = fmaf(s_w[o], fw[o * (Ec * Wc)], acc);

    // wait for tokens (normally ready long before the stream finishes)
    if (k == 0)
        while (*(volatile int*)&d_tokready < Bc) __nanosleep(32);
    __syncthreads();
    __threadfence();

    int toks[Bc];
#pragma unroll
    for (int b = 0; b < Bc; b++)
        toks[b] = d_tok[b * Wc + k];

    const int wid = k >> 5, lid = k & 31;
#pragma unroll
    for (int b = 0; b < Bc; b++) {
        float v = s_emb[toks[b] * 129 + e] * acc;   // conflict-free: bank=(tok+e)%32
#pragma unroll
        for (int off = 16; off; off >>= 1)
            v += __shfl_down_sync(0xffffffffu, v, off);
        if (lid == 0) sp[b][wid] = v;
    }
    __syncthreads();
    if (k < Bc)
        d_part[k * GBLK + e] = sp[k][0] + sp[k][1] + sp[k][2] + sp[k][3];
    __threadfence();
    __syncthreads();
    if (k == 0) atomicAdd(&d_arrive, 1);
}

extern "C" void kernel_launch(void* const* d_in, const int* in_sizes, int n_in,
                              void* d_out, int out_size) {
    const void*  x     = d_in[0];                      // [16,2048] int64 or int32
    const float* emb   = (const float*)d_in[1];        // [7,128]
    const float* fc_w  = (const float*)d_in[2];        // [128,16384]
    const float* fc_b  = (const float*)d_in[3];        // [128]
    const float* out_w = (const float*)d_in[4];        // [1,128]
    const float* out_b = (const float*)d_in[5];        // [1]
    float* out = (float*)d_out;                        // [16]

    fused_kernel<<<GBLK + Bc, NT>>>(x, emb, fc_w, fc_b, out_w, out_b, out);
}